// round 17
// baseline (speedup 1.0000x reference)
#include <cuda_runtime.h>
#include <cuda_fp16.h>

#define IMG_H 512
#define IMG_W 512
#define HW (IMG_H * IMG_W)

// y-lerped fp16 tables: T[b][py][xc(16)][z(8)][32c]  (32 MB each).
// Only z is data-dependent at pixel time; y interpolation is baked here in
// fp32 (one fp16 rounding), so the fused kernel gathers 4 corners, not 8.
__device__ __half t1h[8 * 512 * 16 * 8 * 32];
__device__ __half t2h[8 * 512 * 16 * 8 * 32];   // 27 real channels + 5 zero pad

__global__ __launch_bounds__(256) void build_ylerp_tables(
    const float* __restrict__ g1, const float* __restrict__ g2)
{
    const int i = blockIdx.x * 256 + threadIdx.x;   // 524288 threads
    const int z  = i & 7;
    const int xc = (i >> 3) & 15;
    const int py = (i >> 7) & 511;
    const int b  = i >> 16;

    const float fy = (float)py * (15.0f / 512.0f);  // exact
    const int y0 = (int)fy;                         // 0..14
    const float wy = fy - (float)y0;
    const int o0 = y0 * 16 + xc;
    const int o1 = o0 + 16;                         // y1 = y0+1 <= 15 always

    const int toff = ((b * 512 + py) * 16 + xc) * 256 + z * 32;

    __half* t1 = t1h + toff;
#pragma unroll 8
    for (int c = 0; c < 32; c++) {
        const float* gp = g1 + ((b * 32 + c) * 8 + z) * 256;
        const float a = gp[o0];
        t1[c] = __float2half(fmaf(wy, gp[o1] - a, a));
    }
    __half* t2 = t2h + toff;
#pragma unroll 8
    for (int c = 0; c < 32; c++) {
        float v = 0.0f;
        if (c < 27) {
            const float* gp = g2 + ((b * 27 + c) * 8 + z) * 256;
            const float a = gp[o0];
            v = fmaf(wy, gp[o1] - a, a);
        }
        t2[c] = __float2half(v);
    }
}

__device__ __forceinline__ float tanh_approx(float x) {
    float y;
    asm("tanh.approx.f32 %0, %1;" : "=f"(y) : "f"(x));
    return y;
}
typedef unsigned long long u64;
__device__ __forceinline__ u64 pk2(float lo, float hi) {
    u64 r;
    asm("mov.b64 %0, {%1, %2};" : "=l"(r) : "f"(lo), "f"(hi));
    return r;
}
__device__ __forceinline__ void upk2(float& lo, float& hi, u64 p) {
    asm("mov.b64 {%0, %1}, %2;" : "=f"(lo), "=f"(hi) : "l"(p));
}
__device__ __forceinline__ u64 fma2q(u64 a, u64 b, u64 c) {
    u64 d;
    asm("fma.rn.f32x2 %0, %1, %2, %3;" : "=l"(d) : "l"(a), "l"(b), "l"(c));
    return d;
}
__device__ __forceinline__ u64 add2q(u64 a, u64 b) {
    u64 d;
    asm("add.rn.f32x2 %0, %1, %2;" : "=l"(d) : "l"(a), "l"(b));
    return d;
}
__device__ __forceinline__ u64 h2f2(__half2 h) {
    u64 r;
    unsigned int u = *(unsigned int*)&h;
    asm("{\n\t.reg .b16 l, h;\n\t.reg .f32 fl, fh;\n\t"
        "mov.b32 {l, h}, %1;\n\t"
        "cvt.f32.f16 fl, l;\n\t"
        "cvt.f32.f16 fh, h;\n\t"
        "mov.b64 %0, {fl, fh};\n\t}" : "=l"(r) : "r"(u));
    return r;
}
__device__ __forceinline__ __half2 u2h(unsigned int u) { return *(__half2*)&u; }

// x-lerp (fp16, exact weights) at z0 and z1, then z-lerp in f32x2.
__device__ __forceinline__ u64 xz_interp(
    unsigned a0, unsigned a1, unsigned b0, unsigned b1,
    __half2 wx0h, __half2 wx1h, u64 wzq)
{
    const __half2 s0 = __hfma2(wx1h, u2h(a1), __hmul2(wx0h, u2h(a0)));
    const __half2 s1 = __hfma2(wx1h, u2h(b1), __hmul2(wx0h, u2h(b0)));
    const u64 A = h2f2(s0);
    const u64 B = h2f2(s1);
    const u64 d = add2q(B, A ^ 0x8000000080000000ULL);  // exact B - A
    return fma2q(wzq, d, A);                            // A + wz*(B-A), wz fp32
}

__global__ __launch_bounds__(256, 4) void bgrid_fused_kernel(
    const float* __restrict__ src,
    const float* __restrict__ w1, const float* __restrict__ b1,
    const float* __restrict__ w2, const float* __restrict__ b2,
    const float* __restrict__ w3, const float* __restrict__ b3,
    const float* __restrict__ w4, const float* __restrict__ b4,
    float* __restrict__ out)
{
    __shared__ float2 sp1[8][3];
    __shared__ float2 b1p[8];
    __shared__ float  sw2[16];
    __shared__ float2 sp3[8][8];
    __shared__ float2 b3p[8];
    __shared__ float  sw4[16];
    __shared__ float  sb2s, sb4s;

    const int tid = threadIdx.x;
    if (tid < 24) {
        const int op = tid / 3, jj = tid - op * 3;
        sp1[op][jj] = make_float2(w1[(2 * op) * 3 + jj], w1[(2 * op + 1) * 3 + jj]);
    }
    if (tid < 8) {
        b1p[tid] = make_float2(b1[2 * tid], b1[2 * tid + 1]);
        b3p[tid] = make_float2(b3[2 * tid], b3[2 * tid + 1]);
    }
    if (tid < 16) { sw2[tid] = w2[tid]; sw4[tid] = w4[tid]; }
    if (tid < 64) {
        const int op = tid >> 3, q = tid & 7;
        sp3[op][q] = make_float2(w3[(2 * op) * 8 + q], w3[(2 * op + 1) * 8 + q]);
    }
    if (tid == 0) { sb2s = b2[0]; sb4s = b4[0]; }
    __syncthreads();

    const int idx = blockIdx.x * 256 + tid;
    const int px = idx & 511;
    const int py = (idx >> 9) & 511;
    const int pb = idx >> 18;

    // ---- src pixel ----
    const float* srcp = src + (pb * 3) * HW + py * IMG_W + px;
    const float s0 = srcp[0];
    const float s1 = srcp[HW];
    const float s2 = srcp[2 * HW];
    const u64 sap[4] = {pk2(s0, s0), pk2(s1, s1), pk2(s2, s2), pk2(1.0f, 1.0f)};

    // ---- guide NN #1 ----
    float g = sb2s;
#pragma unroll
    for (int op = 0; op < 8; op++) {
        u64 t2 = *(const u64*)&b1p[op];
        t2 = fma2q(sap[0], *(const u64*)&sp1[op][0], t2);
        t2 = fma2q(sap[1], *(const u64*)&sp1[op][1], t2);
        t2 = fma2q(sap[2], *(const u64*)&sp1[op][2], t2);
        float lo, hi; upk2(lo, hi, t2);
        lo = fmaxf(lo, 0.0f); hi = fmaxf(hi, 0.0f);
        g = fmaf(sw2[2 * op], lo, g);
        g = fmaf(sw2[2 * op + 1], hi, g);
    }
    g = tanh_approx(g);

    // ---- x lattice (y already baked into the tables) ----
    const float fx = (float)px * (15.0f / 512.0f);
    const int x0 = (int)fx;
    const float wx = fx - (float)x0;             // exact multiple of 1/512
    const __half2 wx0h = __float2half2_rn(1.0f - wx);
    const __half2 wx1h = __float2half2_rn(wx);

    // table row for this (b, py): 16 xc-blocks of 256 halfs (8z x 32c)
    const int rowoff = ((pb * 512 + py) * 16) * 256;
    const int cb0 = x0 * 256;
    const int cb1 = cb0 + 256;

    // ---- z for slice 1 ----
    float fz = fminf(fmaxf((g + 1.0f) * 3.5f, 0.0f), 7.0f);
    int z0 = (int)fz;
    if (z0 > 7) z0 = 7;
    int z1 = min(z0 + 1, 7);
    u64 wzq = pk2(fz - (float)z0, fz - (float)z0);

    // ---- slice grid1 (4 corners per j) -> hidp[4] ----
    u64 hidp[4];
#pragma unroll
    for (int e = 0; e < 4; e++) hidp[e] = pk2(0.0f, 0.0f);
    {
        const uint4* q0 = (const uint4*)(t1h + rowoff + cb0);
        const uint4* q1 = (const uint4*)(t1h + rowoff + cb1);
        const int zs0 = z0 * 4, zs1 = z1 * 4;
#pragma unroll
        for (int j = 0; j < 4; j++) {
            const uint4 a0 = __ldg(q0 + zs0 + j);
            const uint4 a1 = __ldg(q1 + zs0 + j);
            const uint4 b0 = __ldg(q0 + zs1 + j);
            const uint4 b1v = __ldg(q1 + zs1 + j);
            u64 v;
            v = xz_interp(a0.x, a1.x, b0.x, b1v.x, wx0h, wx1h, wzq);
            hidp[0] = fma2q(v, sap[j], hidp[0]);
            v = xz_interp(a0.y, a1.y, b0.y, b1v.y, wx0h, wx1h, wzq);
            hidp[1] = fma2q(v, sap[j], hidp[1]);
            v = xz_interp(a0.z, a1.z, b0.z, b1v.z, wx0h, wx1h, wzq);
            hidp[2] = fma2q(v, sap[j], hidp[2]);
            v = xz_interp(a0.w, a1.w, b0.w, b1v.w, wx0h, wx1h, wzq);
            hidp[3] = fma2q(v, sap[j], hidp[3]);
        }
    }
    float hid[8];
#pragma unroll
    for (int e = 0; e < 4; e++) {
        float lo, hi; upk2(lo, hi, hidp[e]);
        hid[2 * e]     = fmaxf(lo, 0.0f);
        hid[2 * e + 1] = fmaxf(hi, 0.0f);
    }

    // ---- guide NN #2 ----
    u64 hd[8];
#pragma unroll
    for (int q = 0; q < 8; q++) hd[q] = pk2(hid[q], hid[q]);
    float g2a = sb4s;
#pragma unroll
    for (int op = 0; op < 8; op++) {
        u64 t2 = *(const u64*)&b3p[op];
#pragma unroll
        for (int q = 0; q < 8; q++)
            t2 = fma2q(hd[q], *(const u64*)&sp3[op][q], t2);
        float lo, hi; upk2(lo, hi, t2);
        lo = fmaxf(lo, 0.0f); hi = fmaxf(hi, 0.0f);
        g2a = fmaf(sw4[2 * op], lo, g2a);
        g2a = fmaf(sw4[2 * op + 1], hi, g2a);
    }
    g2a = tanh_approx(g2a);

    // ---- z for slice 2 ----
    fz = fminf(fmaxf((g2a + 1.0f) * 3.5f, 0.0f), 7.0f);
    z0 = (int)fz;
    if (z0 > 7) z0 = 7;
    z1 = min(z0 + 1, 7);
    wzq = pk2(fz - (float)z0, fz - (float)z0);

    // ---- slice grid2 -> out[3] ----
    float m2[11];
#pragma unroll
    for (int q = 0; q < 8; q++) m2[q] = hid[q];
    m2[8] = 1.0f; m2[9] = 0.0f; m2[10] = 0.0f;

    float r[3] = {0.0f, 0.0f, 0.0f};
    {
        const uint4* q0 = (const uint4*)(t2h + rowoff + cb0);
        const uint4* q1 = (const uint4*)(t2h + rowoff + cb1);
        const int zs0 = z0 * 4, zs1 = z1 * 4;
#pragma unroll
        for (int j = 0; j < 4; j++) {
            const uint4 a0 = __ldg(q0 + zs0 + j);
            const uint4 a1 = __ldg(q1 + zs0 + j);
            const uint4 b0 = __ldg(q0 + zs1 + j);
            const uint4 b1v = __ldg(q1 + zs1 + j);
            float lo, hi;
            u64 v;
            {
                v = xz_interp(a0.x, a1.x, b0.x, b1v.x, wx0h, wx1h, wzq);
                upk2(lo, hi, v);
                const int c = 8 * j;
                r[c % 3]       = fmaf(lo, m2[c / 3], r[c % 3]);
                r[(c + 1) % 3] = fmaf(hi, m2[(c + 1) / 3], r[(c + 1) % 3]);
            }
            {
                v = xz_interp(a0.y, a1.y, b0.y, b1v.y, wx0h, wx1h, wzq);
                upk2(lo, hi, v);
                const int c = 8 * j + 2;
                r[c % 3]       = fmaf(lo, m2[c / 3], r[c % 3]);
                r[(c + 1) % 3] = fmaf(hi, m2[(c + 1) / 3], r[(c + 1) % 3]);
            }
            {
                v = xz_interp(a0.z, a1.z, b0.z, b1v.z, wx0h, wx1h, wzq);
                upk2(lo, hi, v);
                const int c = 8 * j + 4;
                r[c % 3]       = fmaf(lo, m2[c / 3], r[c % 3]);
                r[(c + 1) % 3] = fmaf(hi, m2[(c + 1) / 3], r[(c + 1) % 3]);
            }
            {
                v = xz_interp(a0.w, a1.w, b0.w, b1v.w, wx0h, wx1h, wzq);
                upk2(lo, hi, v);
                const int c = 8 * j + 6;
                r[c % 3]       = fmaf(lo, m2[c / 3], r[c % 3]);
                r[(c + 1) % 3] = fmaf(hi, m2[(c + 1) / 3], r[(c + 1) % 3]);
            }
        }
    }

    float* outp = out + (pb * 3) * HW + py * IMG_W + px;
    outp[0]      = r[0];
    outp[HW]     = r[1];
    outp[2 * HW] = r[2];
}

extern "C" void kernel_launch(void* const* d_in, const int* in_sizes, int n_in,
                              void* d_out, int out_size) {
    const float* src   = (const float*)d_in[0];
    const float* grid1 = (const float*)d_in[1];
    const float* grid2 = (const float*)d_in[2];
    const float* w1    = (const float*)d_in[3];
    const float* b1    = (const float*)d_in[4];
    const float* w2    = (const float*)d_in[5];
    const float* b2    = (const float*)d_in[6];
    const float* w3    = (const float*)d_in[7];
    const float* b3    = (const float*)d_in[8];
    const float* w4    = (const float*)d_in[9];
    const float* b4    = (const float*)d_in[10];
    float* out = (float*)d_out;

    // Pre-pass: y-lerp both grids into per-row fp16 tables.
    build_ylerp_tables<<<2048, 256>>>(grid1, grid2);

    const int total = 8 * IMG_H * IMG_W;
    bgrid_fused_kernel<<<total / 256, 256>>>(src,
                                             w1, b1, w2, b2, w3, b3, w4, b4,
                                             out);
}